// round 6
// baseline (speedup 1.0000x reference)
#include <cuda_runtime.h>

// Problem constants (fixed shapes from reference)
#define BB    32
#define HH    32
#define DD    128
#define KVHH  8
#define GG    4      // GQA group = H/KVH
#define PP    2048
#define TT    64     // tokens per page
#define PPS   64     // pages per sequence
#define NSPLIT 8
#define NWARPS 4
#define PAGES_PER_SPLIT 8          // (NSPLIT*PAGES_PER_SPLIT)*TT = 4096 = PPS*TT
#define CHUNK (PAGES_PER_SPLIT*TT) // 512 tokens per split
#define NPART (NSPLIT*NWARPS)      // 32 partials per (b,kvh)

// Scratch for split-KV partials (static device globals: allocation-guard safe)
__device__ float g_ml[BB*KVHH*NPART*GG*2];                 // (m, l) pairs
__device__ float g_acc[(size_t)BB*KVHH*NPART*GG*DD];       // unnormalized P·V accumulators (16 MB)

// ---------------------------------------------------------------------------
// Kernel 1: per-(b, kvh, split) flash-decode partial.
// 4 warps per CTA; each warp owns whole 64-token pages (contiguous 32KB rows).
// Lane l holds dims [4l, 4l+4) of q/k/v (float4, perfectly coalesced 512B rows).
// Online softmax per warp; partial (m, l, acc) written to global scratch.
// ---------------------------------------------------------------------------

// Process one token given its K and V float4 fragments (already loaded).
__device__ __forceinline__ void pa_token(
    const float4 kv, const float4 vv,
    const float4 (&fq)[GG], float (&m)[GG], float (&l)[GG], float4 (&acc)[GG])
{
    float s[GG];
#pragma unroll
    for (int g = 0; g < GG; g++)
        s[g] = fq[g].x*kv.x + fq[g].y*kv.y + fq[g].z*kv.z + fq[g].w*kv.w;

    // butterfly reduce 4 scores across the warp (all lanes end with sums)
#pragma unroll
    for (int off = 16; off; off >>= 1) {
#pragma unroll
        for (int g = 0; g < GG; g++)
            s[g] += __shfl_xor_sync(0xffffffffu, s[g], off);
    }

#pragma unroll
    for (int g = 0; g < GG; g++) {
        if (s[g] > m[g]) {                    // warp-uniform branch
            const float sc = __expf(m[g] - s[g]);
            l[g] *= sc;
            acc[g].x *= sc; acc[g].y *= sc; acc[g].z *= sc; acc[g].w *= sc;
            m[g] = s[g];
        }
        const float p = __expf(s[g] - m[g]);
        l[g] += p;
        acc[g].x += p*vv.x; acc[g].y += p*vv.y;
        acc[g].z += p*vv.z; acc[g].w += p*vv.w;
    }
}

__global__ __launch_bounds__(NWARPS*32) void pa_partial(
    const float* __restrict__ q,
    const float* __restrict__ k_pages,
    const float* __restrict__ v_pages,
    const int*   __restrict__ lengths,
    const int*   __restrict__ page_indices)
{
    const int split = blockIdx.x;
    const int kvh   = blockIdx.y;
    const int b     = blockIdx.z;
    const int tid   = threadIdx.x;
    const int w     = tid >> 5;
    const int lane  = tid & 31;

    const int len = lengths[b];

    // Load the 4 query-head fragments for this lane (16 floats)
    float4 fq[GG];
#pragma unroll
    for (int g = 0; g < GG; g++)
        fq[g] = *(const float4*)(q + ((size_t)b*HH + (size_t)kvh*GG + g)*DD + lane*4);

    float m[GG], l[GG];
    float4 acc[GG];
#pragma unroll
    for (int g = 0; g < GG; g++) {
        m[g] = -1e30f; l[g] = 0.f;
        acc[g] = make_float4(0.f, 0.f, 0.f, 0.f);
    }

    // Each warp handles pages {w, w+NWARPS} within this split's 8 pages
    for (int pp = w; pp < PAGES_PER_SPLIT; pp += NWARPS) {
        const int sbase = split*CHUNK + pp*TT;        // first global token of this page slot
        if (sbase >= len) break;                       // monotonic in pp -> safe
        const int page = page_indices[b*PPS + split*PAGES_PER_SPLIT + pp]; // uniform load
        const int nt = (len - sbase < TT) ? (len - sbase) : TT;

        const float* kb = k_pages + (((size_t)kvh*PP + page)*TT)*DD + lane*4;
        const float* vb = v_pages + (((size_t)kvh*PP + page)*TT)*DD + lane*4;

        if (nt == TT) {
            // Fast path: full page. 2-deep software pipeline: issue token t+1's
            // loads before processing token t, so the 577-cyc DRAM latency
            // overlaps the shuffle/exp chain. unroll 2 -> >=4 LDG.128 in flight.
            float4 kv = *(const float4*)(kb);
            float4 vv = *(const float4*)(vb);
#pragma unroll 2
            for (int t = 0; t < TT; t++) {
                float4 kn, vn;
                if (t + 1 < TT) {
                    kn = *(const float4*)(kb + (size_t)(t+1)*DD);
                    vn = *(const float4*)(vb + (size_t)(t+1)*DD);
                }
                pa_token(kv, vv, fq, m, l, acc);
                kv = kn; vv = vn;
            }
        } else {
            for (int t = 0; t < nt; t++) {
                const float4 kv = *(const float4*)(kb + (size_t)t*DD);
                const float4 vv = *(const float4*)(vb + (size_t)t*DD);
                pa_token(kv, vv, fq, m, l, acc);
            }
        }
    }

    // Write this warp's partial
    const int part = ((b*KVHH + kvh)*NSPLIT + split)*NWARPS + w;
#pragma unroll
    for (int g = 0; g < GG; g++) {
        if (lane == 0) {
            g_ml[((size_t)part*GG + g)*2 + 0] = m[g];
            g_ml[((size_t)part*GG + g)*2 + 1] = l[g];
        }
        *(float4*)(g_acc + ((size_t)part*GG + g)*DD + lane*4) = acc[g];
    }
}

// ---------------------------------------------------------------------------
// Kernel 2: combine NPART partials per (b, kvh, g) into the final output head.
// One 128-thread block per output head; thread t owns dim t.
// ---------------------------------------------------------------------------
__global__ __launch_bounds__(DD) void pa_combine(float* __restrict__ out)
{
    const int g   = blockIdx.x;
    const int kvh = blockIdx.y;
    const int b   = blockIdx.z;
    const int tid = threadIdx.x;

    __shared__ float wsh[NPART];
    __shared__ float ssum;

    const int base_part = (b*KVHH + kvh)*NPART;

    if (tid < NPART) {
        const float mv = g_ml[((size_t)(base_part + tid)*GG + g)*2 + 0];
        const float lv = g_ml[((size_t)(base_part + tid)*GG + g)*2 + 1];
        float M = mv;
#pragma unroll
        for (int off = 16; off; off >>= 1)
            M = fmaxf(M, __shfl_xor_sync(0xffffffffu, M, off));
        const float wgt = __expf(mv - M);   // 0 for empty partials (mv = -1e30)
        float s = wgt * lv;
#pragma unroll
        for (int off = 16; off; off >>= 1)
            s += __shfl_xor_sync(0xffffffffu, s, off);
        wsh[tid] = wgt;
        if (tid == 0) ssum = s;
    }
    __syncthreads();

    float o = 0.f;
#pragma unroll 4
    for (int p = 0; p < NPART; p++) {
        o += wsh[p] * g_acc[((size_t)(base_part + p)*GG + g)*DD + tid];
    }
    out[((size_t)b*HH + (size_t)kvh*GG + g)*DD + tid] = o / ssum;
}

extern "C" void kernel_launch(void* const* d_in, const int* in_sizes, int n_in,
                              void* d_out, int out_size)
{
    const float* q            = (const float*)d_in[0];
    const float* k_pages      = (const float*)d_in[1];
    const float* v_pages      = (const float*)d_in[2];
    const int*   lengths      = (const int*)d_in[3];
    const int*   page_indices = (const int*)d_in[4];
    float* out = (float*)d_out;

    dim3 grid1(NSPLIT, KVHH, BB);
    pa_partial<<<grid1, NWARPS*32>>>(q, k_pages, v_pages, lengths, page_indices);

    dim3 grid2(GG, KVHH, BB);
    pa_combine<<<grid2, DD>>>(out);
}

// round 12
// speedup vs baseline: 1.3761x; 1.3761x over previous
#include <cuda_runtime.h>

// Problem constants (fixed shapes from reference)
#define BB    32
#define HH    32
#define DD    128
#define KVHH  8
#define GG    4      // GQA group = H/KVH
#define PP    2048
#define TT    64     // tokens per page
#define PPS   64     // pages per sequence
#define NSPLIT 8
#define NWARPS 4
#define PAGES_PER_SPLIT 8          // (NSPLIT*PAGES_PER_SPLIT)*TT = 4096 = PPS*TT
#define CHUNK (PAGES_PER_SPLIT*TT) // 512 tokens per split
#define NPART (NSPLIT*NWARPS)      // 32 partials per (b,kvh)

// Scratch for split-KV partials (static device globals: allocation-guard safe)
__device__ float g_ml[BB*KVHH*NPART*GG*2];                 // (m, l) pairs
__device__ float g_acc[(size_t)BB*KVHH*NPART*GG*DD];       // unnormalized P·V accumulators (16 MB)

typedef unsigned long long u64;   // packed f32x2 container

// ---- f32x2 packed-math helpers (sm_103a FFMA2 path; ptxas won't auto-fuse) ----
__device__ __forceinline__ u64 pack2(float a, float b) {
    u64 r; asm("mov.b64 %0,{%1,%2};" : "=l"(r) : "f"(a), "f"(b)); return r;
}
__device__ __forceinline__ float2 unpack2(u64 v) {
    float2 r; asm("mov.b64 {%0,%1},%2;" : "=f"(r.x), "=f"(r.y) : "l"(v)); return r;
}
__device__ __forceinline__ void fma2(u64& d, u64 a, u64 b) {   // d = a*b + d (elementwise)
    asm("fma.rn.f32x2 %0,%1,%2,%0;" : "+l"(d) : "l"(a), "l"(b));
}
__device__ __forceinline__ void mul2(u64& d, u64 a) {          // d *= a
    asm("mul.rn.f32x2 %0,%0,%1;" : "+l"(d) : "l"(a));
}
__device__ __forceinline__ u64 add2(u64 a, u64 b) {
    u64 r; asm("add.rn.f32x2 %0,%1,%2;" : "=l"(r) : "l"(a), "l"(b)); return r;
}

// ---------------------------------------------------------------------------
// Kernel 1: per-(b, kvh, split) flash-decode partial.
// 4 warps/CTA; each warp owns whole 64-token pages. HALF-WARP per token:
// lanes 0-15 process even tokens, 16-31 odd tokens of each pair. Lane hl owns
// dims {4hl..4hl+4} U {64+4hl..64+4hl+4} (two float4 chunks -> coalesced:
// one LDG.128 covers 256B of token A + 256B of token B, rows contiguous).
// Scores/accumulators kept in packed f32x2; online softmax per half-warp;
// halves merged at the end; partial (m,l,acc) to global scratch.
// ---------------------------------------------------------------------------

__device__ __forceinline__ void pa_tok(
    const float* __restrict__ kb, const float* __restrict__ vb,
    int tok, bool ok,
    const u64 (&fq)[GG][4], float (&m)[GG], float (&l)[GG], u64 (&acc)[GG][4])
{
    const float* kr = kb + (size_t)tok * DD;
    const float* vr = vb + (size_t)tok * DD;
    const ulonglong2 k0 = *(const ulonglong2*)(kr);
    const ulonglong2 k1 = *(const ulonglong2*)(kr + 64);
    const ulonglong2 v0 = *(const ulonglong2*)(vr);
    const ulonglong2 v1 = *(const ulonglong2*)(vr + 64);
    const u64 kp[4] = {k0.x, k0.y, k1.x, k1.y};
    const u64 vp[4] = {v0.x, v0.y, v1.x, v1.y};

    // QK dot: 4 packed FMA2 per head
    float s[GG];
#pragma unroll
    for (int g = 0; g < GG; g++) {
        u64 sp = 0ull;
#pragma unroll
        for (int j = 0; j < 4; j++) fma2(sp, kp[j], fq[g][j]);
        const float2 hz = unpack2(sp);
        s[g] = hz.x + hz.y;
    }

    // 4-level butterfly within each 16-lane half (offsets stay inside half)
#pragma unroll
    for (int off = 8; off; off >>= 1) {
#pragma unroll
        for (int g = 0; g < GG; g++)
            s[g] += __shfl_xor_sync(0xffffffffu, s[g], off);
    }

    // online-softmax max update (rare; warp-voted branch, per-half uniform)
    bool need = false;
    if (ok) {
#pragma unroll
        for (int g = 0; g < GG; g++) need |= (s[g] > m[g]);
    }
    if (__any_sync(0xffffffffu, need)) {
#pragma unroll
        for (int g = 0; g < GG; g++) {
            if (ok && s[g] > m[g]) {
                const float sc = __expf(m[g] - s[g]);
                l[g] *= sc;
                const u64 scp = pack2(sc, sc);
#pragma unroll
                for (int j = 0; j < 4; j++) mul2(acc[g][j], scp);
                m[g] = s[g];
            }
        }
    }

    if (ok) {
#pragma unroll
        for (int g = 0; g < GG; g++) {
            const float p = __expf(s[g] - m[g]);
            l[g] += p;
            const u64 ppk = pack2(p, p);
#pragma unroll
            for (int j = 0; j < 4; j++) fma2(acc[g][j], vp[j], ppk);
        }
    }
}

__global__ __launch_bounds__(NWARPS*32) void pa_partial(
    const float* __restrict__ q,
    const float* __restrict__ k_pages,
    const float* __restrict__ v_pages,
    const int*   __restrict__ lengths,
    const int*   __restrict__ page_indices)
{
    const int split = blockIdx.x;
    const int kvh   = blockIdx.y;
    const int b     = blockIdx.z;
    const int tid   = threadIdx.x;
    const int w     = tid >> 5;
    const int lane  = tid & 31;
    const int hw    = lane >> 4;   // which half-warp (token parity)
    const int hl    = lane & 15;   // lane within half (dim slice)

    const int len = lengths[b];

    // Packed query fragments: fq[g][0..1] = dims [4hl..4hl+4), [2..3] = [64+4hl..)
    u64 fq[GG][4];
#pragma unroll
    for (int g = 0; g < GG; g++) {
        const float* qb = q + ((size_t)b*HH + (size_t)kvh*GG + g)*DD + 4*hl;
        const ulonglong2 a = *(const ulonglong2*)(qb);
        const ulonglong2 c = *(const ulonglong2*)(qb + 64);
        fq[g][0] = a.x; fq[g][1] = a.y; fq[g][2] = c.x; fq[g][3] = c.y;
    }

    float m[GG], l[GG];
    u64 acc[GG][4];
#pragma unroll
    for (int g = 0; g < GG; g++) {
        m[g] = -1e30f; l[g] = 0.f;
#pragma unroll
        for (int j = 0; j < 4; j++) acc[g][j] = 0ull;   // bits of (0.f,0.f)
    }

    // Each warp handles pages {w, w+NWARPS} within this split's 8 pages
    for (int pp = w; pp < PAGES_PER_SPLIT; pp += NWARPS) {
        const int sbase = split*CHUNK + pp*TT;         // first global token of page slot
        if (sbase >= len) break;                        // monotonic in pp -> safe
        const int page = page_indices[b*PPS + split*PAGES_PER_SPLIT + pp];
        const int nt = (len - sbase < TT) ? (len - sbase) : TT;

        const float* kb = k_pages + (((size_t)kvh*PP + page)*TT)*DD + 4*hl;
        const float* vb = v_pages + (((size_t)kvh*PP + page)*TT)*DD + 4*hl;

        if (nt == TT) {
#pragma unroll 2
            for (int t0 = 0; t0 < TT; t0 += 2)
                pa_tok(kb, vb, t0 + hw, true, fq, m, l, acc);
        } else {
            for (int t0 = 0; t0 < nt; t0 += 2) {
                const int tok = t0 + hw;
                const bool ok = tok < nt;
                pa_tok(kb, vb, ok ? tok : nt-1, ok, fq, m, l, acc);
            }
        }
    }

    // Merge the two half-warp streams (lane l and l+16 own the same dims)
#pragma unroll
    for (int g = 0; g < GG; g++) {
        const float mo = __shfl_xor_sync(0xffffffffu, m[g], 16);
        const float M  = fmaxf(m[g], mo);
        const float sc = __expf(m[g] - M);       // own rescale (0 if never ran)
        l[g] *= sc;
        const u64 scp = pack2(sc, sc);
#pragma unroll
        for (int j = 0; j < 4; j++) mul2(acc[g][j], scp);
        l[g] += __shfl_xor_sync(0xffffffffu, l[g], 16);
#pragma unroll
        for (int j = 0; j < 4; j++) {
            const u64 o = __shfl_xor_sync(0xffffffffu, acc[g][j], 16);
            acc[g][j] = add2(acc[g][j], o);
        }
        m[g] = M;
    }

    // Write this warp's partial. Lane<16 stores chunk A (dim 4hl),
    // lane>=16 stores chunk B (dim 64+4hl) -> full 128 dims per g.
    const int part = ((b*KVHH + kvh)*NSPLIT + split)*NWARPS + w;
#pragma unroll
    for (int g = 0; g < GG; g++) {
        if (lane == 0) {
            g_ml[((size_t)part*GG + g)*2 + 0] = m[g];
            g_ml[((size_t)part*GG + g)*2 + 1] = l[g];
        }
        const u64 s0 = hw ? acc[g][2] : acc[g][0];
        const u64 s1 = hw ? acc[g][3] : acc[g][1];
        ulonglong2 st; st.x = s0; st.y = s1;
        *(ulonglong2*)(g_acc + ((size_t)part*GG + g)*DD + hw*64 + 4*hl) = st;
    }
}

// ---------------------------------------------------------------------------
// Kernel 2: combine NPART partials per (b, kvh, g) into the final output head.
// One 128-thread block per output head; thread t owns dim t.
// Slots never written stay (m=0,l=0,acc=0): they only raise the shared max M,
// which cancels exactly in the num/denom ratio -> correct.
// ---------------------------------------------------------------------------
__global__ __launch_bounds__(DD) void pa_combine(float* __restrict__ out)
{
    const int g   = blockIdx.x;
    const int kvh = blockIdx.y;
    const int b   = blockIdx.z;
    const int tid = threadIdx.x;

    __shared__ float wsh[NPART];
    __shared__ float ssum;

    const int base_part = (b*KVHH + kvh)*NPART;

    if (tid < NPART) {
        const float mv = g_ml[((size_t)(base_part + tid)*GG + g)*2 + 0];
        const float lv = g_ml[((size_t)(base_part + tid)*GG + g)*2 + 1];
        float M = mv;
#pragma unroll
        for (int off = 16; off; off >>= 1)
            M = fmaxf(M, __shfl_xor_sync(0xffffffffu, M, off));
        const float wgt = __expf(mv - M);   // 0 for empty partials (mv = -1e30)
        float s = wgt * lv;
#pragma unroll
        for (int off = 16; off; off >>= 1)
            s += __shfl_xor_sync(0xffffffffu, s, off);
        wsh[tid] = wgt;
        if (tid == 0) ssum = s;
    }
    __syncthreads();

    float o = 0.f;
#pragma unroll 4
    for (int p = 0; p < NPART; p++) {
        o += wsh[p] * g_acc[((size_t)(base_part + p)*GG + g)*DD + tid];
    }
    out[((size_t)b*HH + (size_t)kvh*GG + g)*DD + tid] = o / ssum;
}

extern "C" void kernel_launch(void* const* d_in, const int* in_sizes, int n_in,
                              void* d_out, int out_size)
{
    const float* q            = (const float*)d_in[0];
    const float* k_pages      = (const float*)d_in[1];
    const float* v_pages      = (const float*)d_in[2];
    const int*   lengths      = (const int*)d_in[3];
    const int*   page_indices = (const int*)d_in[4];
    float* out = (float*)d_out;

    dim3 grid1(NSPLIT, KVHH, BB);
    pa_partial<<<grid1, NWARPS*32>>>(q, k_pages, v_pages, lengths, page_indices);

    dim3 grid2(GG, KVHH, BB);
    pa_combine<<<grid2, DD>>>(out);
}

// round 14
// speedup vs baseline: 1.6159x; 1.1743x over previous
#include <cuda_runtime.h>

// Problem constants (fixed shapes from reference)
#define BB    32
#define HH    32
#define DD    128
#define KVHH  8
#define GG    4      // GQA group = H/KVH
#define PP    2048
#define TT    64     // tokens per page
#define PPS   64     // pages per sequence
#define NSPLIT 8
#define NWARPS 4
#define PAGES_PER_SPLIT 8          // (NSPLIT*PAGES_PER_SPLIT)*TT = 4096 = PPS*TT
#define CHUNK (PAGES_PER_SPLIT*TT) // 512 tokens per split
#define NPART NSPLIT               // 8 partials per (b,kvh) after in-CTA merge

// Scratch for split-KV partials (static device globals: allocation-guard safe)
__device__ float g_ml[BB*KVHH*NPART*GG*2];                 // (m, l) pairs
__device__ float g_acc[(size_t)BB*KVHH*NPART*GG*DD];       // unnormalized P·V (4 MB)

typedef unsigned long long u64;   // packed f32x2 container

// ---- f32x2 packed-math helpers (sm_103a FFMA2 path; ptxas won't auto-fuse) ----
__device__ __forceinline__ u64 pack2(float a, float b) {
    u64 r; asm("mov.b64 %0,{%1,%2};" : "=l"(r) : "f"(a), "f"(b)); return r;
}
__device__ __forceinline__ float2 unpack2(u64 v) {
    float2 r; asm("mov.b64 {%0,%1},%2;" : "=f"(r.x), "=f"(r.y) : "l"(v)); return r;
}
__device__ __forceinline__ void fma2(u64& d, u64 a, u64 b) {   // d = a*b + d
    asm("fma.rn.f32x2 %0,%1,%2,%0;" : "+l"(d) : "l"(a), "l"(b));
}
__device__ __forceinline__ void mul2(u64& d, u64 a) {          // d *= a
    asm("mul.rn.f32x2 %0,%0,%1;" : "+l"(d) : "l"(a));
}

// ---------------------------------------------------------------------------
// Kernel 1: per-(b, kvh, split) flash-decode partial.
// 4 warps/CTA; each warp owns whole 64-token pages. HALF-WARP per token:
// lanes 0-15 even tokens, 16-31 odd tokens. Lane hl owns dims
// {4hl..4hl+3} U {64+4hl..64+4hl+3}. Explicit 1-pair prefetch keeps
// 8 LDG.128 in flight per warp. 4 warp-partials merged in-CTA via smem.
// ---------------------------------------------------------------------------

__device__ __forceinline__ void pa_load(
    const float* __restrict__ kb, const float* __restrict__ vb, int tok,
    u64 (&kp)[4], u64 (&vp)[4])
{
    const float* kr = kb + (size_t)tok * DD;
    const float* vr = vb + (size_t)tok * DD;
    const ulonglong2 k0 = *(const ulonglong2*)(kr);
    const ulonglong2 k1 = *(const ulonglong2*)(kr + 64);
    const ulonglong2 v0 = *(const ulonglong2*)(vr);
    const ulonglong2 v1 = *(const ulonglong2*)(vr + 64);
    kp[0] = k0.x; kp[1] = k0.y; kp[2] = k1.x; kp[3] = k1.y;
    vp[0] = v0.x; vp[1] = v0.y; vp[2] = v1.x; vp[3] = v1.y;
}

__device__ __forceinline__ void pa_compute(
    const u64 (&kp)[4], const u64 (&vp)[4], bool ok,
    const u64 (&fq)[GG][4], float (&m)[GG], float (&l)[GG], u64 (&acc)[GG][4])
{
    // QK dot: 4 packed FMA2 per head
    float s[GG];
#pragma unroll
    for (int g = 0; g < GG; g++) {
        u64 sp = 0ull;
#pragma unroll
        for (int j = 0; j < 4; j++) fma2(sp, kp[j], fq[g][j]);
        const float2 hz = unpack2(sp);
        s[g] = hz.x + hz.y;
    }

    // 4-level butterfly within each 16-lane half
#pragma unroll
    for (int off = 8; off; off >>= 1) {
#pragma unroll
        for (int g = 0; g < GG; g++)
            s[g] += __shfl_xor_sync(0xffffffffu, s[g], off);
    }

    // online-softmax max update (voted, rare)
    bool need = false;
    if (ok) {
#pragma unroll
        for (int g = 0; g < GG; g++) need |= (s[g] > m[g]);
    }
    if (__any_sync(0xffffffffu, need)) {
#pragma unroll
        for (int g = 0; g < GG; g++) {
            if (ok && s[g] > m[g]) {
                const float sc = __expf(m[g] - s[g]);
                l[g] *= sc;
                const u64 scp = pack2(sc, sc);
#pragma unroll
                for (int j = 0; j < 4; j++) mul2(acc[g][j], scp);
                m[g] = s[g];
            }
        }
    }

    if (ok) {
#pragma unroll
        for (int g = 0; g < GG; g++) {
            const float p = __expf(s[g] - m[g]);
            l[g] += p;
            const u64 ppk = pack2(p, p);
#pragma unroll
            for (int j = 0; j < 4; j++) fma2(acc[g][j], vp[j], ppk);
        }
    }
}

__global__ __launch_bounds__(NWARPS*32) void pa_partial(
    const float* __restrict__ q,
    const float* __restrict__ k_pages,
    const float* __restrict__ v_pages,
    const int*   __restrict__ lengths,
    const int*   __restrict__ page_indices)
{
    const int split = blockIdx.x;
    const int kvh   = blockIdx.y;
    const int b     = blockIdx.z;
    const int tid   = threadIdx.x;
    const int w     = tid >> 5;
    const int lane  = tid & 31;
    const int hw    = lane >> 4;   // half-warp (token parity)
    const int hl    = lane & 15;   // lane within half (dim slice)

    __shared__ float sm_acc[NWARPS][GG][DD];   // 8 KB
    __shared__ float sm_ml[NWARPS][GG][2];

    const int len = lengths[b];

    // Packed query fragments
    u64 fq[GG][4];
#pragma unroll
    for (int g = 0; g < GG; g++) {
        const float* qb = q + ((size_t)b*HH + (size_t)kvh*GG + g)*DD + 4*hl;
        const ulonglong2 a = *(const ulonglong2*)(qb);
        const ulonglong2 c = *(const ulonglong2*)(qb + 64);
        fq[g][0] = a.x; fq[g][1] = a.y; fq[g][2] = c.x; fq[g][3] = c.y;
    }

    float m[GG], l[GG];
    u64 acc[GG][4];
#pragma unroll
    for (int g = 0; g < GG; g++) {
        m[g] = -1e30f; l[g] = 0.f;
#pragma unroll
        for (int j = 0; j < 4; j++) acc[g][j] = 0ull;
    }

    // Each warp handles pages {w, w+NWARPS} within this split's 8 pages
    for (int pp = w; pp < PAGES_PER_SPLIT; pp += NWARPS) {
        const int sbase = split*CHUNK + pp*TT;
        if (sbase >= len) break;                 // monotonic in pp -> safe
        const int page = page_indices[b*PPS + split*PAGES_PER_SPLIT + pp];
        const int nt = (len - sbase < TT) ? (len - sbase) : TT;

        const float* kb = k_pages + (((size_t)kvh*PP + page)*TT)*DD + 4*hl;
        const float* vb = v_pages + (((size_t)kvh*PP + page)*TT)*DD + 4*hl;

        if (nt == TT) {
            // Fast path: 1-pair software pipeline -> 8 LDG.128 in flight
            u64 kp[4], vp[4], kn[4], vn[4];
            pa_load(kb, vb, hw, kp, vp);
#pragma unroll 2
            for (int t0 = 0; t0 < TT; t0 += 2) {
                if (t0 + 2 < TT) pa_load(kb, vb, t0 + 2 + hw, kn, vn);
                pa_compute(kp, vp, true, fq, m, l, acc);
#pragma unroll
                for (int j = 0; j < 4; j++) { kp[j] = kn[j]; vp[j] = vn[j]; }
            }
        } else {
            for (int t0 = 0; t0 < nt; t0 += 2) {
                const int tok = t0 + hw;
                const bool ok = tok < nt;
                u64 kp[4], vp[4];
                pa_load(kb, vb, ok ? tok : nt-1, kp, vp);
                pa_compute(kp, vp, ok, fq, m, l, acc);
            }
        }
    }

    // Merge the two half-warp streams (lane l and l+16 own the same dims)
#pragma unroll
    for (int g = 0; g < GG; g++) {
        const float mo = __shfl_xor_sync(0xffffffffu, m[g], 16);
        const float M  = fmaxf(m[g], mo);
        const float sc = __expf(m[g] - M);
        l[g] *= sc;
        const u64 scp = pack2(sc, sc);
#pragma unroll
        for (int j = 0; j < 4; j++) mul2(acc[g][j], scp);
        l[g] += __shfl_xor_sync(0xffffffffu, l[g], 16);
#pragma unroll
        for (int j = 0; j < 4; j++) {
            const u64 o = __shfl_xor_sync(0xffffffffu, acc[g][j], 16);
            const float2 aa = unpack2(acc[g][j]);
            const float2 bb = unpack2(o);
            acc[g][j] = pack2(aa.x + bb.x, aa.y + bb.y);
        }
        m[g] = M;
    }

    // Stage warp partial into smem (lane<16: dims A, lane>=16: dims B)
#pragma unroll
    for (int g = 0; g < GG; g++) {
        if (lane == 0) { sm_ml[w][g][0] = m[g]; sm_ml[w][g][1] = l[g]; }
        const u64 s0 = hw ? acc[g][2] : acc[g][0];
        const u64 s1 = hw ? acc[g][3] : acc[g][1];
        ulonglong2 st; st.x = s0; st.y = s1;
        *(ulonglong2*)(&sm_acc[w][g][hw*64 + 4*hl]) = st;
    }
    __syncthreads();

    // Cross-warp merge: warp g reduces the 4 warp-partials of head g.
    {
        const int g = w;
        float mw[NWARPS], lw[NWARPS];
#pragma unroll
        for (int w2 = 0; w2 < NWARPS; w2++) {
            mw[w2] = sm_ml[w2][g][0];
            lw[w2] = sm_ml[w2][g][1];
        }
        float M = mw[0];
#pragma unroll
        for (int w2 = 1; w2 < NWARPS; w2++) M = fmaxf(M, mw[w2]);
        float lt = 0.f;
        float4 o = make_float4(0.f, 0.f, 0.f, 0.f);
#pragma unroll
        for (int w2 = 0; w2 < NWARPS; w2++) {
            const float wgt = __expf(mw[w2] - M);   // 0 for empty partials
            lt += wgt * lw[w2];
            const float4 a = *(const float4*)(&sm_acc[w2][g][4*lane]);
            o.x += wgt*a.x; o.y += wgt*a.y; o.z += wgt*a.z; o.w += wgt*a.w;
        }
        const int part = (b*KVHH + kvh)*NSPLIT + split;
        if (lane == 0) {
            g_ml[((size_t)part*GG + g)*2 + 0] = M;
            g_ml[((size_t)part*GG + g)*2 + 1] = lt;
        }
        *(float4*)(g_acc + ((size_t)part*GG + g)*DD + 4*lane) = o;
    }
}

// ---------------------------------------------------------------------------
// Kernel 2: combine NPART(=8) partials per (b, kvh). One 128-thread block per
// (b,kvh); warp g owns head g; lane owns 4 dims (float4). 8 independent
// LDG.128 fully unrolled -> MLP 8; no syncthreads.
// ---------------------------------------------------------------------------
__global__ __launch_bounds__(GG*32) void pa_combine(float* __restrict__ out)
{
    const int bk   = blockIdx.x;          // b*KVHH + kvh
    const int g    = threadIdx.x >> 5;
    const int lane = threadIdx.x & 31;

    const int base = bk * NPART;

    // lanes 0..7 hold partial p=lane's (m,l)
    float mv = -1e30f, lv = 0.f;
    if (lane < NPART) {
        mv = g_ml[((size_t)(base + lane)*GG + g)*2 + 0];
        lv = g_ml[((size_t)(base + lane)*GG + g)*2 + 1];
    }
    float M = mv;
#pragma unroll
    for (int off = 16; off; off >>= 1)
        M = fmaxf(M, __shfl_xor_sync(0xffffffffu, M, off));
    const float wgt = __expf(mv - M);     // 0 on padding lanes
    float s = wgt * lv;
#pragma unroll
    for (int off = 16; off; off >>= 1)
        s += __shfl_xor_sync(0xffffffffu, s, off);

    float4 o = make_float4(0.f, 0.f, 0.f, 0.f);
#pragma unroll
    for (int p = 0; p < NPART; p++) {
        const float wp = __shfl_sync(0xffffffffu, wgt, p);
        const float4 a = *(const float4*)(g_acc + ((size_t)(base + p)*GG + g)*DD + 4*lane);
        o.x += wp*a.x; o.y += wp*a.y; o.z += wp*a.z; o.w += wp*a.w;
    }
    const float inv = 1.f / s;
    o.x *= inv; o.y *= inv; o.z *= inv; o.w *= inv;
    *(float4*)(out + ((size_t)bk*GG + g)*DD + 4*lane) = o;
}

extern "C" void kernel_launch(void* const* d_in, const int* in_sizes, int n_in,
                              void* d_out, int out_size)
{
    const float* q            = (const float*)d_in[0];
    const float* k_pages      = (const float*)d_in[1];
    const float* v_pages      = (const float*)d_in[2];
    const int*   lengths      = (const int*)d_in[3];
    const int*   page_indices = (const int*)d_in[4];
    float* out = (float*)d_out;

    dim3 grid1(NSPLIT, KVHH, BB);
    pa_partial<<<grid1, NWARPS*32>>>(q, k_pages, v_pages, lengths, page_indices);

    pa_combine<<<BB*KVHH, GG*32>>>(out);
}